// round 15
// baseline (speedup 1.0000x reference)
#include <cuda_runtime.h>
#include <cuda_fp16.h>
#include <cstdint>

#define BB 2
#define NN 4096
#define DD 768

constexpr int BM = 128, BN = 128;
constexpr int BKb   = 64;
constexpr int STG_A = BM * BKb * 2;        // 16384 B
constexpr int STG   = 2 * STG_A;           // 32768 B
constexpr int NSTG  = 3;                   // 98304 B

// ---------------------------------------------------------------------------
// Scratch
// ---------------------------------------------------------------------------
__device__ __half g_xh[BB * NN * DD];            // x in fp16
__device__ __half g_wc[3 * DD * DD];             // [Wq^T;Wk^T;Wv^T] fp16, K-major
__device__ __half g_qh[BB * NN * DD];
__device__ __half g_kh[BB * NN * DD];
__device__ __half g_vt[BB * NN * DD];            // V^T per batch [DD, NN]
__device__ __half g_p[(size_t)BB * NN * NN];     // unnormalized exp(scores), fp16
__device__ float  g_r[BB * NN];                  // row sums (atomics)

// ---------------------------------------------------------------------------
// Helpers
// ---------------------------------------------------------------------------
__device__ __forceinline__ uint32_t smem_u32(const void* p) {
    uint32_t a;
    asm("{ .reg .u64 t; cvta.to.shared.u64 t, %1; cvt.u32.u64 %0, t; }" : "=r"(a) : "l"(p));
    return a;
}
__device__ __forceinline__ uint32_t sw128(uint32_t o) { return o ^ (((o) >> 3) & 0x70); }

// ldmatrix stays volatile (must not migrate across __syncthreads)
__device__ __forceinline__ void ldm_x4(uint32_t* r, uint32_t a) {
    asm volatile("ldmatrix.sync.aligned.m8n8.x4.shared.b16 {%0,%1,%2,%3}, [%4];"
                 : "=r"(r[0]), "=r"(r[1]), "=r"(r[2]), "=r"(r[3]) : "r"(a));
}
// mma: NON-volatile, register-only -> scheduler may interleave with ldm stream
__device__ __forceinline__ void mma16816(float* c, const uint32_t* a, const uint32_t* b) {
    asm("mma.sync.aligned.m16n8k16.row.col.f32.f16.f16.f32 "
        "{%0,%1,%2,%3},{%4,%5,%6,%7},{%8,%9},{%0,%1,%2,%3};"
        : "+f"(c[0]), "+f"(c[1]), "+f"(c[2]), "+f"(c[3])
        : "r"(a[0]), "r"(a[1]), "r"(a[2]), "r"(a[3]), "r"(b[0]), "r"(b[1]));
}
__device__ __forceinline__ uint32_t h2u(__half2 h) { return *(uint32_t*)&h; }
__device__ __forceinline__ void cpa16(uint32_t dst, const void* src) {
    asm volatile("cp.async.cg.shared.global [%0], [%1], 16;" :: "r"(dst), "l"(src));
}

// ===========================================================================
// Mainloop: BK=64, 3-stage cp.async, CTA 128x128, 128 threads,
// 4 warps of 64x64 (2x2). acc[4][8][4] = 128 regs.
// KSTEP pipelined: B-frags + A0 first, then prefetch A[mi+1] under MMA group mi.
// ===========================================================================
#define MAINLOOP_BODY(Ag, Bg, KLEN, LDA, LDB)                                  \
    float acc[4][8][4];                                                        \
    _Pragma("unroll") for (int mi = 0; mi < 4; mi++)                           \
    _Pragma("unroll") for (int ni = 0; ni < 8; ni++)                           \
    _Pragma("unroll") for (int r = 0; r < 4; r++) acc[mi][ni][r] = 0.f;        \
    auto LOAD = [&](int t, int stg) {                                          \
        const int k0 = t * BKb;                                                \
        const uint32_t da = smem_u32(sm + stg * STG);                          \
        const uint32_t db = da + STG_A;                                        \
        _Pragma("unroll") for (int i = 0; i < 8; i++) {                        \
            const int idx = tid + i * 128;                                     \
            const int r = idx >> 3, c = idx & 7;                               \
            cpa16(da + sw128(r * 128 + c * 16), Ag + (size_t)(m0 + r) * (LDA) + k0 + c * 8); \
            cpa16(db + sw128(r * 128 + c * 16), Bg + (size_t)(n0 + r) * (LDB) + k0 + c * 8); \
        }                                                                      \
        asm volatile("cp.async.commit_group;" ::: "memory");                   \
    };                                                                         \
    const int mrow  = wm * 64 + (lane & 15);                                   \
    const int acolb = (lane & 16);                                             \
    const int nrow  = wn * 64 + (lane & 7) + ((lane & 16) >> 1);               \
    const int bcolb = (lane & 8) << 1;                                         \
    auto KSTEP = [&](int stg, int ks) {                                        \
        const uint32_t baseA = smem_u32(sm + stg * STG);                       \
        const uint32_t baseB = baseA + STG_A;                                  \
        uint32_t a[4][4], b[4][4];                                             \
        _Pragma("unroll") for (int n2 = 0; n2 < 4; n2++)                       \
            ldm_x4(b[n2], baseB + sw128((nrow + n2 * 16) * 128 + ks * 2 + bcolb)); \
        ldm_x4(a[0], baseA + sw128((mrow) * 128 + ks * 2 + acolb));            \
        _Pragma("unroll") for (int mi = 0; mi < 4; mi++) {                     \
            if (mi < 3)                                                        \
                ldm_x4(a[mi + 1], baseA + sw128((mrow + (mi + 1) * 16) * 128 + ks * 2 + acolb)); \
            _Pragma("unroll") for (int ni = 0; ni < 8; ni++)                   \
                mma16816(acc[mi][ni], a[mi], &b[ni >> 1][(ni & 1) * 2]);       \
        }                                                                      \
    };                                                                         \
    const int NT = (KLEN) / BKb;                                               \
    LOAD(0, 0); LOAD(1, 1);                                                    \
    int stg = 0;                                                               \
    for (int t = 0; t < NT; t++) {                                             \
        asm volatile("cp.async.wait_group 1;" ::: "memory");                   \
        __syncthreads();                                                       \
        const int sn = (stg + 2 >= NSTG) ? stg + 2 - NSTG : stg + 2;           \
        if (t + 2 < NT) LOAD(t + 2, sn);                                       \
        else asm volatile("cp.async.commit_group;" ::: "memory");              \
        KSTEP(stg, 0); KSTEP(stg, 16); KSTEP(stg, 32); KSTEP(stg, 48);         \
        stg = (stg + 1 >= NSTG) ? 0 : stg + 1;                                 \
    }

#define GEMM_PRELUDE                                                           \
    extern __shared__ __align__(1024) char sm[];                               \
    const int tid  = threadIdx.x;                                              \
    const int lane = tid & 31;                                                 \
    const int warp = tid >> 5;                                                 \
    const int wm = warp >> 1, wn = warp & 1;

// ---------------------------------------------------------------------------
// Merged projection kernel, 1152 CTAs (bid<768: Q,K; bid>=768: V^T tiles)
// ---------------------------------------------------------------------------
__global__ __launch_bounds__(128, 2)
void gemm_proj(const __half* __restrict__ Xh, const __half* __restrict__ Wc,
               __half* __restrict__ qp, __half* __restrict__ kp,
               __half* __restrict__ vtp)
{
    GEMM_PRELUDE
    const int bid = blockIdx.x;
    const bool is_vt = (bid >= 768);
    const __half *Ag, *Bg;
    int m0, n0, z = 0;
    if (!is_vt) {
        n0 = (bid % 12) * BN;
        m0 = (bid / 12) * BM;
        Ag = Xh;
        Bg = Wc;
    } else {
        const int t = bid - 768;
        z = t / 192;
        const int r = t % 192;
        n0 = (r % 32) * BN;
        m0 = (r / 32) * BM;
        Ag = Wc + 2 * DD * DD;
        Bg = Xh + (size_t)z * NN * DD;
    }

    MAINLOOP_BODY(Ag, Bg, DD, DD, DD)

    if (!is_vt) {
        __half* dst = (n0 < DD) ? qp : kp;
        const int c0 = (n0 < DD) ? n0 : n0 - DD;
#pragma unroll
        for (int mi = 0; mi < 4; mi++) {
            const int r = m0 + wm * 64 + mi * 16 + (lane >> 2);
#pragma unroll
            for (int ni = 0; ni < 8; ni++) {
                const int c = c0 + wn * 64 + ni * 8 + (lane & 3) * 2;
                *(__half2*)(dst + (size_t)r * DD + c) =
                    __floats2half2_rn(acc[mi][ni][0], acc[mi][ni][1]);
                *(__half2*)(dst + (size_t)(r + 8) * DD + c) =
                    __floats2half2_rn(acc[mi][ni][2], acc[mi][ni][3]);
            }
        }
    } else {
        __half* C = vtp + (size_t)z * NN * DD;    // [DD, NN]
#pragma unroll
        for (int mi = 0; mi < 4; mi++) {
            const int r = m0 + wm * 64 + mi * 16 + (lane >> 2);
#pragma unroll
            for (int ni = 0; ni < 8; ni++) {
                const int c = n0 + wn * 64 + ni * 8 + (lane & 3) * 2;
                *(__half2*)(C + (size_t)r * NN + c) =
                    __floats2half2_rn(acc[mi][ni][0], acc[mi][ni][1]);
                *(__half2*)(C + (size_t)(r + 8) * NN + c) =
                    __floats2half2_rn(acc[mi][ni][2], acc[mi][ni][3]);
            }
        }
    }
}

// ---------------------------------------------------------------------------
// Score GEMM: P = exp(scale * Q @ K^T) fp16, fused row-sum atomics
// ---------------------------------------------------------------------------
__global__ __launch_bounds__(128, 2)
void gemm_score(const __half* __restrict__ Qg, const __half* __restrict__ Kg,
                __half* __restrict__ Pg, float* __restrict__ rsum, float alpha)
{
    GEMM_PRELUDE
    const int z = blockIdx.z;
    const __half* Ag = Qg + (size_t)z * NN * DD;
    const __half* Bg = Kg + (size_t)z * NN * DD;
    const int m0 = blockIdx.y * BM;
    const int n0 = blockIdx.x * BN;

    MAINLOOP_BODY(Ag, Bg, DD, DD, DD)

    __half* C = Pg + (size_t)z * NN * NN;
    float* rs = rsum + z * NN;
#pragma unroll
    for (int mi = 0; mi < 4; mi++) {
        const int r = m0 + wm * 64 + mi * 16 + (lane >> 2);
        float s0 = 0.f, s1 = 0.f;
#pragma unroll
        for (int ni = 0; ni < 8; ni++) {
            const int c = n0 + wn * 64 + ni * 8 + (lane & 3) * 2;
            __half2 h0 = __floats2half2_rn(__expf(alpha * acc[mi][ni][0]),
                                           __expf(alpha * acc[mi][ni][1]));
            __half2 h1 = __floats2half2_rn(__expf(alpha * acc[mi][ni][2]),
                                           __expf(alpha * acc[mi][ni][3]));
            *(__half2*)(C + (size_t)r * NN + c)       = h0;
            *(__half2*)(C + (size_t)(r + 8) * NN + c) = h1;
            const float2 f0 = __half22float2(h0), f1 = __half22float2(h1);
            s0 += f0.x + f0.y;
            s1 += f1.x + f1.y;
        }
        s0 += __shfl_xor_sync(0xffffffffu, s0, 1);
        s0 += __shfl_xor_sync(0xffffffffu, s0, 2);
        s1 += __shfl_xor_sync(0xffffffffu, s1, 1);
        s1 += __shfl_xor_sync(0xffffffffu, s1, 2);
        if ((lane & 3) == 0) {
            atomicAdd(rs + r, s0);
            atomicAdd(rs + r + 8, s1);
        }
    }
}

// ---------------------------------------------------------------------------
// PV GEMM: out fp32 = (P @ V) / rowsum   (V supplied as V^T, K-major)
// ---------------------------------------------------------------------------
__global__ __launch_bounds__(128, 2)
void gemm_pv(const __half* __restrict__ Pg, const __half* __restrict__ Vt,
             float* __restrict__ Og, const float* __restrict__ rsum)
{
    GEMM_PRELUDE
    const int z = blockIdx.z;
    const __half* Ag = Pg + (size_t)z * NN * NN;
    const __half* Bg = Vt + (size_t)z * NN * DD;
    const int m0 = blockIdx.y * BM;
    const int n0 = blockIdx.x * BN;

    MAINLOOP_BODY(Ag, Bg, NN, NN, NN)

    float* C = Og + (size_t)z * NN * DD;
    const float* rs = rsum + z * NN;
#pragma unroll
    for (int mi = 0; mi < 4; mi++) {
        const int r = m0 + wm * 64 + mi * 16 + (lane >> 2);
        const float s0 = 1.0f / rs[r], s1 = 1.0f / rs[r + 8];
#pragma unroll
        for (int ni = 0; ni < 8; ni++) {
            const int c = n0 + wn * 64 + ni * 8 + (lane & 3) * 2;
            *(float2*)(C + (size_t)r * DD + c) =
                make_float2(s0 * acc[mi][ni][0], s0 * acc[mi][ni][1]);
            *(float2*)(C + (size_t)(r + 8) * DD + c) =
                make_float2(s1 * acc[mi][ni][2], s1 * acc[mi][ni][3]);
        }
    }
}

// ---------------------------------------------------------------------------
// x fp32 -> fp16 (+ zero the rowsum buffer)
// ---------------------------------------------------------------------------
__global__ __launch_bounds__(256)
void convert_x(const float* __restrict__ x, __half* __restrict__ xh,
               float* __restrict__ rv)
{
    if (blockIdx.x < 8) {
        ((float4*)rv)[blockIdx.x * 256 + threadIdx.x] = make_float4(0.f, 0.f, 0.f, 0.f);
    }
    const int i = blockIdx.x * 256 + threadIdx.x;
#pragma unroll
    for (int j = 0; j < 8; j++) {
        const int idx = i + j * gridDim.x * 256;
        const float4 f = *(const float4*)(x + idx * 4);
        uint2 u;
        u.x = h2u(__floats2half2_rn(f.x, f.y));
        u.y = h2u(__floats2half2_rn(f.z, f.w));
        *(uint2*)(xh + idx * 4) = u;
    }
}

// ---------------------------------------------------------------------------
// Weight prep: W[768,768] fp32 [K,N] -> Wc[w][n][k] fp16 (transposed)
// ---------------------------------------------------------------------------
__global__ __launch_bounds__(256)
void prep_w(const float* __restrict__ w0, const float* __restrict__ w1,
            const float* __restrict__ w2, __half* __restrict__ wc)
{
    __shared__ float tile[32][33];
    const int z = blockIdx.z;
    const float* src = (z == 0) ? w0 : ((z == 1) ? w1 : w2);
    __half* dst = wc + (size_t)z * DD * DD;
    const int k0 = blockIdx.x * 32;
    const int n0 = blockIdx.y * 32;
    const int tid = threadIdx.x;
    const int r = tid >> 5, c = tid & 31;

#pragma unroll
    for (int i = 0; i < 4; i++)
        tile[r + i * 8][c] = src[(size_t)(k0 + r + i * 8) * DD + n0 + c];
    __syncthreads();
#pragma unroll
    for (int i = 0; i < 4; i++)
        dst[(size_t)(n0 + r + i * 8) * DD + k0 + c] = __float2half_rn(tile[c][r + i * 8]);
}

// ---------------------------------------------------------------------------
extern "C" void kernel_launch(void* const* d_in, const int* in_sizes, int n_in,
                              void* d_out, int out_size)
{
    const float* x  = (const float*)d_in[0];
    const float* Wq = (const float*)d_in[1];
    const float* Wk = (const float*)d_in[2];
    const float* Wv = (const float*)d_in[3];
    float* out = (float*)d_out;

    __half *xh, *wc, *qh, *kh, *vt, *ph;
    float* rv;
    cudaGetSymbolAddress((void**)&xh, g_xh);
    cudaGetSymbolAddress((void**)&wc, g_wc);
    cudaGetSymbolAddress((void**)&qh, g_qh);
    cudaGetSymbolAddress((void**)&kh, g_kh);
    cudaGetSymbolAddress((void**)&vt, g_vt);
    cudaGetSymbolAddress((void**)&ph, g_p);
    cudaGetSymbolAddress((void**)&rv, g_r);

    const int SMEM = NSTG * STG;   // 98304
    static bool attr_set = false;
    if (!attr_set) {
        cudaFuncSetAttribute(gemm_score, cudaFuncAttributeMaxDynamicSharedMemorySize, SMEM);
        cudaFuncSetAttribute(gemm_pv,    cudaFuncAttributeMaxDynamicSharedMemorySize, SMEM);
        cudaFuncSetAttribute(gemm_proj,  cudaFuncAttributeMaxDynamicSharedMemorySize, SMEM);
        attr_set = true;
    }

    const float scale = 0.03608439182435161f;  // 1/sqrt(768)

    convert_x<<<768, 256>>>(x, xh, rv);
    prep_w<<<dim3(DD / 32, DD / 32, 3), 256>>>(Wq, Wk, Wv, wc);

    // merged Q,K + V^T projections (128-thread CTAs)
    gemm_proj<<<1152, 128, SMEM>>>(xh, wc, qh, kh, vt);

    // score GEMM with fused exp + rowsum atomics
    gemm_score<<<dim3(NN / BN, NN / BM, BB), 128, SMEM>>>(qh, kh, ph, rv, scale);

    // PV with fused normalization
    gemm_pv<<<dim3(DD / BN, NN / BM, BB), 128, SMEM>>>(ph, vt, out, rv);
}

// round 16
// speedup vs baseline: 1.1076x; 1.1076x over previous
#include <cuda_runtime.h>
#include <cuda_fp16.h>
#include <cstdint>

#define BB 2
#define NN 4096
#define DD 768

constexpr int BM = 128, BN = 128;
constexpr int BKb   = 64;
constexpr int STG_A = BM * BKb * 2;        // 16384 B
constexpr int STG   = 2 * STG_A;           // 32768 B
constexpr int NSTG  = 3;                   // 98304 B

// ---------------------------------------------------------------------------
// Scratch
// ---------------------------------------------------------------------------
__device__ __half g_xh[BB * NN * DD];            // x in fp16
__device__ __half g_wc[3 * DD * DD];             // [Wq^T;Wk^T;Wv^T] fp16, K-major
__device__ __half g_qh[BB * NN * DD];
__device__ __half g_kh[BB * NN * DD];
__device__ __half g_vt[BB * NN * DD];            // V^T per batch [DD, NN]
__device__ __half g_p[(size_t)BB * NN * NN];     // unnormalized exp(scores), fp16
__device__ float  g_r[BB * NN];                  // row sums (atomics)

// ---------------------------------------------------------------------------
// Helpers
// ---------------------------------------------------------------------------
__device__ __forceinline__ uint32_t smem_u32(const void* p) {
    uint32_t a;
    asm("{ .reg .u64 t; cvta.to.shared.u64 t, %1; cvt.u32.u64 %0, t; }" : "=r"(a) : "l"(p));
    return a;
}
__device__ __forceinline__ uint32_t sw128(uint32_t o) { return o ^ (((o) >> 3) & 0x70); }

__device__ __forceinline__ void ldm_x4(uint32_t* r, uint32_t a) {
    asm volatile("ldmatrix.sync.aligned.m8n8.x4.shared.b16 {%0,%1,%2,%3}, [%4];"
                 : "=r"(r[0]), "=r"(r[1]), "=r"(r[2]), "=r"(r[3]) : "r"(a));
}
__device__ __forceinline__ void mma16816(float* c, const uint32_t* a, const uint32_t* b) {
    asm volatile(
        "mma.sync.aligned.m16n8k16.row.col.f32.f16.f16.f32 "
        "{%0,%1,%2,%3},{%4,%5,%6,%7},{%8,%9},{%0,%1,%2,%3};"
        : "+f"(c[0]), "+f"(c[1]), "+f"(c[2]), "+f"(c[3])
        : "r"(a[0]), "r"(a[1]), "r"(a[2]), "r"(a[3]), "r"(b[0]), "r"(b[1]));
}
__device__ __forceinline__ uint32_t h2u(__half2 h) { return *(uint32_t*)&h; }
__device__ __forceinline__ void cpa16(uint32_t dst, const void* src) {
    asm volatile("cp.async.cg.shared.global [%0], [%1], 16;" :: "r"(dst), "l"(src));
}

// ===========================================================================
// Mainloop (R14-proven): BK=64, 3-stage cp.async, CTA 128x128, 128 threads,
// 4 warps of 64x64 (2x2). acc[4][8][4] = 128 regs.
// ===========================================================================
#define MAINLOOP_BODY(Ag, Bg, KLEN, LDA, LDB)                                  \
    float acc[4][8][4];                                                        \
    _Pragma("unroll") for (int mi = 0; mi < 4; mi++)                           \
    _Pragma("unroll") for (int ni = 0; ni < 8; ni++)                           \
    _Pragma("unroll") for (int r = 0; r < 4; r++) acc[mi][ni][r] = 0.f;        \
    auto LOAD = [&](int t, int stg) {                                          \
        const int k0 = t * BKb;                                                \
        const uint32_t da = smem_u32(sm + stg * STG);                          \
        const uint32_t db = da + STG_A;                                        \
        _Pragma("unroll") for (int i = 0; i < 8; i++) {                        \
            const int idx = tid + i * 128;                                     \
            const int r = idx >> 3, c = idx & 7;                               \
            cpa16(da + sw128(r * 128 + c * 16), Ag + (size_t)(m0 + r) * (LDA) + k0 + c * 8); \
            cpa16(db + sw128(r * 128 + c * 16), Bg + (size_t)(n0 + r) * (LDB) + k0 + c * 8); \
        }                                                                      \
        asm volatile("cp.async.commit_group;" ::: "memory");                   \
    };                                                                         \
    const int mrow  = wm * 64 + (lane & 15);                                   \
    const int acolb = (lane & 16);                                             \
    const int nrow  = wn * 64 + (lane & 7) + ((lane & 16) >> 1);               \
    const int bcolb = (lane & 8) << 1;                                         \
    auto KSTEP = [&](int stg, int ks) {                                        \
        const uint32_t baseA = smem_u32(sm + stg * STG);                       \
        const uint32_t baseB = baseA + STG_A;                                  \
        uint32_t a[4][4], b[4][4];                                             \
        _Pragma("unroll") for (int mi = 0; mi < 4; mi++)                       \
            ldm_x4(a[mi], baseA + sw128((mrow + mi * 16) * 128 + ks * 2 + acolb)); \
        _Pragma("unroll") for (int n2 = 0; n2 < 4; n2++)                       \
            ldm_x4(b[n2], baseB + sw128((nrow + n2 * 16) * 128 + ks * 2 + bcolb)); \
        _Pragma("unroll") for (int mi = 0; mi < 4; mi++)                       \
        _Pragma("unroll") for (int ni = 0; ni < 8; ni++)                       \
            mma16816(acc[mi][ni], a[mi], &b[ni >> 1][(ni & 1) * 2]);           \
    };                                                                         \
    const int NT = (KLEN) / BKb;                                               \
    LOAD(0, 0); LOAD(1, 1);                                                    \
    int stg = 0;                                                               \
    for (int t = 0; t < NT; t++) {                                             \
        asm volatile("cp.async.wait_group 1;" ::: "memory");                   \
        __syncthreads();                                                       \
        const int sn = (stg + 2 >= NSTG) ? stg + 2 - NSTG : stg + 2;           \
        if (t + 2 < NT) LOAD(t + 2, sn);                                       \
        else asm volatile("cp.async.commit_group;" ::: "memory");              \
        KSTEP(stg, 0); KSTEP(stg, 16); KSTEP(stg, 32); KSTEP(stg, 48);         \
        stg = (stg + 1 >= NSTG) ? 0 : stg + 1;                                 \
    }

#define GEMM_PRELUDE                                                           \
    extern __shared__ __align__(1024) char sm[];                               \
    const int tid  = threadIdx.x;                                              \
    const int lane = tid & 31;                                                 \
    const int warp = tid >> 5;                                                 \
    const int wm = warp >> 1, wn = warp & 1;

// ---------------------------------------------------------------------------
// Merged projection kernel, 1152 CTAs (bid<768: Q,K; bid>=768: V^T tiles)
// ---------------------------------------------------------------------------
__global__ __launch_bounds__(128, 2)
void gemm_proj(const __half* __restrict__ Xh, const __half* __restrict__ Wc,
               __half* __restrict__ qp, __half* __restrict__ kp,
               __half* __restrict__ vtp)
{
    GEMM_PRELUDE
    const int bid = blockIdx.x;
    const bool is_vt = (bid >= 768);
    const __half *Ag, *Bg;
    int m0, n0, z = 0;
    if (!is_vt) {
        n0 = (bid % 12) * BN;
        m0 = (bid / 12) * BM;
        Ag = Xh;
        Bg = Wc;
    } else {
        const int t = bid - 768;
        z = t / 192;
        const int r = t % 192;
        n0 = (r % 32) * BN;
        m0 = (r / 32) * BM;
        Ag = Wc + 2 * DD * DD;
        Bg = Xh + (size_t)z * NN * DD;
    }

    MAINLOOP_BODY(Ag, Bg, DD, DD, DD)

    if (!is_vt) {
        __half* dst = (n0 < DD) ? qp : kp;
        const int c0 = (n0 < DD) ? n0 : n0 - DD;
#pragma unroll
        for (int mi = 0; mi < 4; mi++) {
            const int r = m0 + wm * 64 + mi * 16 + (lane >> 2);
#pragma unroll
            for (int ni = 0; ni < 8; ni++) {
                const int c = c0 + wn * 64 + ni * 8 + (lane & 3) * 2;
                *(__half2*)(dst + (size_t)r * DD + c) =
                    __floats2half2_rn(acc[mi][ni][0], acc[mi][ni][1]);
                *(__half2*)(dst + (size_t)(r + 8) * DD + c) =
                    __floats2half2_rn(acc[mi][ni][2], acc[mi][ni][3]);
            }
        }
    } else {
        __half* C = vtp + (size_t)z * NN * DD;    // [DD, NN]
#pragma unroll
        for (int mi = 0; mi < 4; mi++) {
            const int r = m0 + wm * 64 + mi * 16 + (lane >> 2);
#pragma unroll
            for (int ni = 0; ni < 8; ni++) {
                const int c = n0 + wn * 64 + ni * 8 + (lane & 3) * 2;
                *(__half2*)(C + (size_t)r * NN + c) =
                    __floats2half2_rn(acc[mi][ni][0], acc[mi][ni][1]);
                *(__half2*)(C + (size_t)(r + 8) * NN + c) =
                    __floats2half2_rn(acc[mi][ni][2], acc[mi][ni][3]);
            }
        }
    }
}

// ---------------------------------------------------------------------------
// Score GEMM: P = exp(scale * Q @ K^T) fp16, fused row-sum atomics
// ---------------------------------------------------------------------------
__global__ __launch_bounds__(128, 2)
void gemm_score(const __half* __restrict__ Qg, const __half* __restrict__ Kg,
                __half* __restrict__ Pg, float* __restrict__ rsum, float alpha)
{
    GEMM_PRELUDE
    const int z = blockIdx.z;
    const __half* Ag = Qg + (size_t)z * NN * DD;
    const __half* Bg = Kg + (size_t)z * NN * DD;
    const int m0 = blockIdx.y * BM;
    const int n0 = blockIdx.x * BN;

    MAINLOOP_BODY(Ag, Bg, DD, DD, DD)

    __half* C = Pg + (size_t)z * NN * NN;
    float* rs = rsum + z * NN;
#pragma unroll
    for (int mi = 0; mi < 4; mi++) {
        const int r = m0 + wm * 64 + mi * 16 + (lane >> 2);
        float s0 = 0.f, s1 = 0.f;
#pragma unroll
        for (int ni = 0; ni < 8; ni++) {
            const int c = n0 + wn * 64 + ni * 8 + (lane & 3) * 2;
            __half2 h0 = __floats2half2_rn(__expf(alpha * acc[mi][ni][0]),
                                           __expf(alpha * acc[mi][ni][1]));
            __half2 h1 = __floats2half2_rn(__expf(alpha * acc[mi][ni][2]),
                                           __expf(alpha * acc[mi][ni][3]));
            *(__half2*)(C + (size_t)r * NN + c)       = h0;
            *(__half2*)(C + (size_t)(r + 8) * NN + c) = h1;
            const float2 f0 = __half22float2(h0), f1 = __half22float2(h1);
            s0 += f0.x + f0.y;
            s1 += f1.x + f1.y;
        }
        s0 += __shfl_xor_sync(0xffffffffu, s0, 1);
        s0 += __shfl_xor_sync(0xffffffffu, s0, 2);
        s1 += __shfl_xor_sync(0xffffffffu, s1, 1);
        s1 += __shfl_xor_sync(0xffffffffu, s1, 2);
        if ((lane & 3) == 0) {
            atomicAdd(rs + r, s0);
            atomicAdd(rs + r + 8, s1);
        }
    }
}

// ---------------------------------------------------------------------------
// PV GEMM: out fp32 = (P @ V) / rowsum   (V supplied as V^T, K-major)
// ---------------------------------------------------------------------------
__global__ __launch_bounds__(128, 2)
void gemm_pv(const __half* __restrict__ Pg, const __half* __restrict__ Vt,
             float* __restrict__ Og, const float* __restrict__ rsum)
{
    GEMM_PRELUDE
    const int z = blockIdx.z;
    const __half* Ag = Pg + (size_t)z * NN * NN;
    const __half* Bg = Vt + (size_t)z * NN * DD;
    const int m0 = blockIdx.y * BM;
    const int n0 = blockIdx.x * BN;

    MAINLOOP_BODY(Ag, Bg, NN, NN, NN)

    float* C = Og + (size_t)z * NN * DD;
    const float* rs = rsum + z * NN;
#pragma unroll
    for (int mi = 0; mi < 4; mi++) {
        const int r = m0 + wm * 64 + mi * 16 + (lane >> 2);
        const float s0 = 1.0f / rs[r], s1 = 1.0f / rs[r + 8];
#pragma unroll
        for (int ni = 0; ni < 8; ni++) {
            const int c = n0 + wn * 64 + ni * 8 + (lane & 3) * 2;
            *(float2*)(C + (size_t)r * DD + c) =
                make_float2(s0 * acc[mi][ni][0], s0 * acc[mi][ni][1]);
            *(float2*)(C + (size_t)(r + 8) * DD + c) =
                make_float2(s1 * acc[mi][ni][2], s1 * acc[mi][ni][3]);
        }
    }
}

// ---------------------------------------------------------------------------
// Fused prep: bid<768 -> x fp32->fp16 (+ rv zero); bid>=768 -> weight transpose
// ---------------------------------------------------------------------------
__global__ __launch_bounds__(256)
void prep_all(const float* __restrict__ x, __half* __restrict__ xh,
              float* __restrict__ rv,
              const float* __restrict__ w0, const float* __restrict__ w1,
              const float* __restrict__ w2, __half* __restrict__ wc)
{
    const int bid = blockIdx.x;
    if (bid < 768) {
        if (bid < 8) {
            ((float4*)rv)[bid * 256 + threadIdx.x] = make_float4(0.f, 0.f, 0.f, 0.f);
        }
        const int i = bid * 256 + threadIdx.x;
#pragma unroll
        for (int j = 0; j < 8; j++) {
            const int idx = i + j * 768 * 256;
            const float4 f = *(const float4*)(x + idx * 4);
            uint2 u;
            u.x = h2u(__floats2half2_rn(f.x, f.y));
            u.y = h2u(__floats2half2_rn(f.z, f.w));
            *(uint2*)(xh + idx * 4) = u;
        }
    } else {
        __shared__ float tile[32][33];
        const int t = bid - 768;            // 0..1727
        const int z = t / 576;              // which weight
        const int r2 = t % 576;
        const float* src = (z == 0) ? w0 : ((z == 1) ? w1 : w2);
        __half* dst = wc + (size_t)z * DD * DD;
        const int k0 = (r2 % 24) * 32;
        const int n0 = (r2 / 24) * 32;
        const int tid = threadIdx.x;
        const int r = tid >> 5, c = tid & 31;
#pragma unroll
        for (int i = 0; i < 4; i++)
            tile[r + i * 8][c] = src[(size_t)(k0 + r + i * 8) * DD + n0 + c];
        __syncthreads();
#pragma unroll
        for (int i = 0; i < 4; i++)
            dst[(size_t)(n0 + r + i * 8) * DD + k0 + c] = __float2half_rn(tile[c][r + i * 8]);
    }
}

// ---------------------------------------------------------------------------
extern "C" void kernel_launch(void* const* d_in, const int* in_sizes, int n_in,
                              void* d_out, int out_size)
{
    const float* x  = (const float*)d_in[0];
    const float* Wq = (const float*)d_in[1];
    const float* Wk = (const float*)d_in[2];
    const float* Wv = (const float*)d_in[3];
    float* out = (float*)d_out;

    __half *xh, *wc, *qh, *kh, *vt, *ph;
    float* rv;
    cudaGetSymbolAddress((void**)&xh, g_xh);
    cudaGetSymbolAddress((void**)&wc, g_wc);
    cudaGetSymbolAddress((void**)&qh, g_qh);
    cudaGetSymbolAddress((void**)&kh, g_kh);
    cudaGetSymbolAddress((void**)&vt, g_vt);
    cudaGetSymbolAddress((void**)&ph, g_p);
    cudaGetSymbolAddress((void**)&rv, g_r);

    const int SMEM = NSTG * STG;   // 98304
    cudaFuncSetAttribute(gemm_score, cudaFuncAttributeMaxDynamicSharedMemorySize, SMEM);
    cudaFuncSetAttribute(gemm_pv,    cudaFuncAttributeMaxDynamicSharedMemorySize, SMEM);
    cudaFuncSetAttribute(gemm_proj,  cudaFuncAttributeMaxDynamicSharedMemorySize, SMEM);

    const float scale = 0.03608439182435161f;  // 1/sqrt(768)

    // x->fp16 + rowsum zero + weight transpose, single launch
    prep_all<<<768 + 1728, 256>>>(x, xh, rv, Wq, Wk, Wv, wc);

    // merged Q,K + V^T projections (128-thread CTAs)
    gemm_proj<<<1152, 128, SMEM>>>(xh, wc, qh, kh, vt);

    // score GEMM with fused exp + rowsum atomics
    gemm_score<<<dim3(NN / BN, NN / BM, BB), 128, SMEM>>>(qh, kh, ph, rv, scale);

    // PV with fused normalization
    gemm_pv<<<dim3(DD / BN, NN / BM, BB), 128, SMEM>>>(ph, vt, out, rv);
}